// round 15
// baseline (speedup 1.0000x reference)
#include <cuda_runtime.h>
#include <cuda_bf16.h>
#include <math.h>
#include <stdint.h>

#define BB   8
#define NN   2048
#define KK   16
#define CIN  128
#define HID  128
#define COUT 128
#define NNODE (BB * NN)
#define PN   8              // nodes per block in precompute
#define NPB  4              // nodes per block in main kernel
#define ROWB 272            // padded row bytes of x tile (17 x 16B -> LDSM conflict-free)
#define SPLIT_TILE (KK * ROWB)        // 4352 bytes per split
#define NODE_TILE  (2 * SPLIT_TILE)   // 8704 bytes per node (hi + lo)

// scratch: per-node projections  A = h@(W1a-W1b)+b1,  U = h@W1b
__device__ float g_A[NNODE * HID];
__device__ float g_U[NNODE * HID];
// W2, 2-way bf16 split, prepacked in mma.m16n8k16 B-fragment order.
// One 16B slot per (kstep, ntile, lane): .x = hi-split frag, .y = lo-split frag.
__device__ ulonglong2 g_Bfrag[8 * 16 * 32];
__device__ int g_idx_is64;

// ---- f32x2 helpers (precompute kernel) ----
__device__ __forceinline__ unsigned long long ffma2(unsigned long long a,
                                                    unsigned long long b,
                                                    unsigned long long c) {
    unsigned long long d;
    asm("fma.rn.f32x2 %0, %1, %2, %3;" : "=l"(d) : "l"(a), "l"(b), "l"(c));
    return d;
}
__device__ __forceinline__ unsigned long long pack2(float lo, float hi) {
    unsigned long long v;
    asm("mov.b64 %0, {%1, %2};" : "=l"(v) : "f"(lo), "f"(hi));
    return v;
}
__device__ __forceinline__ float2 unpack2(unsigned long long v) {
    float2 r;
    asm("mov.b64 {%0, %1}, %2;" : "=f"(r.x), "=f"(r.y) : "l"(v));
    return r;
}

// Branch-free gelu via Abramowitz-Stegun 7.1.26 erf (abs err <= 1.5e-7).
__device__ __forceinline__ float fast_gelu(float x) {
    const float z  = fabsf(x) * 0.70710678118654752440f;
    const float t  = __fdividef(1.0f, fmaf(0.3275911f, z, 1.0f));
    float p = fmaf(1.061405429f, t, -1.453152027f);
    p = fmaf(p, t, 1.421413741f);
    p = fmaf(p, t, -0.284496736f);
    p = fmaf(p, t, 0.254829592f);
    p = p * t;
    const float e = 1.0f - p * __expf(-z * z);
    return 0.5f * x * (1.0f + copysignf(e, x));
}

__device__ __forceinline__ uint32_t smem_u32(const void* p) {
    uint32_t a;
    asm("{ .reg .u64 t; cvta.to.shared.u64 t, %1; cvt.u32.u64 %0, t; }" : "=r"(a) : "l"(p));
    return a;
}

// ---- warp-level tensor core primitives (sm_80-era, valid on sm_103) ----
__device__ __forceinline__ void ldsm_x4(uint32_t* r, uint32_t addr) {
    asm volatile("ldmatrix.sync.aligned.m8n8.x4.shared.b16 {%0,%1,%2,%3}, [%4];"
                 : "=r"(r[0]), "=r"(r[1]), "=r"(r[2]), "=r"(r[3]) : "r"(addr));
}
__device__ __forceinline__ void mma16816(float* c, const uint32_t* a,
                                         uint32_t b0, uint32_t b1) {
    asm volatile("mma.sync.aligned.m16n8k16.row.col.f32.bf16.bf16.f32 "
                 "{%0,%1,%2,%3}, {%4,%5,%6,%7}, {%8,%9}, {%0,%1,%2,%3};"
                 : "+f"(c[0]), "+f"(c[1]), "+f"(c[2]), "+f"(c[3])
                 : "r"(a[0]), "r"(a[1]), "r"(a[2]), "r"(a[3]), "r"(b0), "r"(b1));
}

__device__ __forceinline__ uint32_t bf16x2_pack(float x, float y) {
    __nv_bfloat162 h = __floats2bfloat162_rn(x, y);   // .x = x in low half
    return *reinterpret_cast<uint32_t*>(&h);
}

// ---------------------------------------------------------------------------
// Precompute A = h@(W1a-W1b)+b1,  U = h@W1b.
// Block 0: idx dtype detect.  Blocks 0..31: also prepack W2 B-fragments
// (both splits packed into one 16B slot).
// ---------------------------------------------------------------------------
__global__ __launch_bounds__(128) void precompute_kernel(
    const float* __restrict__ h,
    const float* __restrict__ W1,
    const float* __restrict__ b1,
    const float* __restrict__ W2,
    const int*   __restrict__ idx_raw)
{
    __shared__ float hs[PN][CIN];
    const int t     = threadIdx.x;
    const int node0 = blockIdx.x * PN;

    if (blockIdx.x == 0 && t < 32) {
        int nz = (idx_raw[2 * t + 1] != 0) | (idx_raw[2 * (t + 32) + 1] != 0);
        unsigned m = __ballot_sync(0xffffffffu, nz);
        if (t == 0) g_idx_is64 = (m == 0u);
    }

    // ---- W2 B-fragment prepack, folded in (blocks 0..31, 128 slots each) ----
    if (blockIdx.x < 32) {
        const int flat = blockIdx.x * 128 + t;   // 0..4095 slots
        const int lane = flat & 31;
        const int nt   = (flat >> 5) & 15;
        const int s    = (flat >> 9) & 7;
        const int tg   = lane & 3;
        const int n    = nt * 8 + (lane >> 2);
        const int kloc[4] = {2 * tg, 2 * tg + 1, 2 * tg + 8, 2 * tg + 9};
        unsigned long long vh = 0ull, vl = 0ull;
        #pragma unroll
        for (int e = 0; e < 4; ++e) {
            const float w = W2[(s * 16 + kloc[e]) * COUT + n];
            const __nv_bfloat16 hi = __float2bfloat16(w);
            const __nv_bfloat16 lo = __float2bfloat16(w - __bfloat162float(hi));
            vh |= (unsigned long long)(*reinterpret_cast<const unsigned short*>(&hi)) << (16 * e);
            vl |= (unsigned long long)(*reinterpret_cast<const unsigned short*>(&lo)) << (16 * e);
        }
        g_Bfrag[flat] = make_ulonglong2(vh, vl);
    }

    #pragma unroll
    for (int i = 0; i < PN; ++i)
        hs[i][t] = h[(size_t)(node0 + i) * CIN + t];
    __syncthreads();

    unsigned long long accA[PN], accU[PN];
    #pragma unroll
    for (int i = 0; i < PN; ++i) { accA[i] = 0ull; accU[i] = 0ull; }

    #pragma unroll 2
    for (int dd = 0; dd < CIN / 4; ++dd) {
        const int d0 = 4 * dd;
        float w1a[4], w1b[4];
        #pragma unroll
        for (int j = 0; j < 4; ++j) {
            w1a[j] = W1[(d0 + j) * HID + t];
            w1b[j] = W1[(CIN + d0 + j) * HID + t];
        }
        const unsigned long long wa01 = pack2(w1a[0] - w1b[0], w1a[1] - w1b[1]);
        const unsigned long long wa23 = pack2(w1a[2] - w1b[2], w1a[3] - w1b[3]);
        const unsigned long long wb01 = pack2(w1b[0], w1b[1]);
        const unsigned long long wb23 = pack2(w1b[2], w1b[3]);
        #pragma unroll
        for (int i = 0; i < PN; ++i) {
            const ulonglong2 m2 = *reinterpret_cast<const ulonglong2*>(&hs[i][d0]);
            accA[i] = ffma2(m2.x, wa01, accA[i]);
            accA[i] = ffma2(m2.y, wa23, accA[i]);
            accU[i] = ffma2(m2.x, wb01, accU[i]);
            accU[i] = ffma2(m2.y, wb23, accU[i]);
        }
    }
    const float bv = b1[t];
    #pragma unroll
    for (int i = 0; i < PN; ++i) {
        const float2 a2 = unpack2(accA[i]);
        const float2 u2 = unpack2(accU[i]);
        g_A[(size_t)(node0 + i) * HID + t] = a2.x + a2.y + bv;
        g_U[(size_t)(node0 + i) * HID + t] = u2.x + u2.y;
    }
}

// ---------------------------------------------------------------------------
// Main kernel: 4 nodes per block, 128 threads (4 warps), 6 blocks/SM.
// Phase A (thread = d-pair): x1 split tiles (fast_gelu, 1-cvt hi pack).
// Phase B (warp = node): hoisted Ah frags; Al re-ldsm'd per s; B-frags via
//         one LDG.128 per (nt,s) slot (hi+lo packed); nt groups of 4 with
//         independent accumulators, split-products interleaved; min/max over
//         M into dead hi-tile smem; unimodal fast_gelu x2; in-warp LayerNorm.
// ---------------------------------------------------------------------------
__global__ __launch_bounds__(128, 6) void edgeconv_mma_kernel(
    const float* __restrict__ pos,
    const int*   __restrict__ idx_raw,
    const float* __restrict__ W1,      // rows 256..258 (rel weights)
    const float* __restrict__ b2,
    const float* __restrict__ gamma,
    const float* __restrict__ beta,
    float*       __restrict__ out)
{
    __shared__ __align__(16) unsigned char xs[NPB * NODE_TILE];   // 34816 B
    __shared__ int   jidx[NPB * KK];
    __shared__ __align__(16) float rel[NPB * KK][4];

    const int t     = threadIdx.x;
    const int lane  = t & 31;
    const int wid   = t >> 5;
    const int node0 = blockIdx.x * NPB;
    const int b     = node0 >> 11;
    const float* pb = pos + (size_t)b * NN * 3;

    // ---- neighbor indices ----
    if (t < NPB * KK) {
        long e = (long)node0 * KK + t;
        jidx[t] = g_idx_is64 ? idx_raw[2 * e] : idx_raw[e];
    }
    __syncthreads();

    // ---- relative positions (192 entries, 128 threads -> strided loop) ----
    for (int s = t; s < NPB * KK * 3; s += 128) {
        const int e = s / 3, c = s - 3 * e;     // e = nn*16 + k
        const int nn = e >> 4;
        const int n  = (node0 + nn) & (NN - 1);
        rel[e][c] = pb[jidx[e] * 3 + c] - pb[n * 3 + c];
    }
    __syncthreads();

    // ---- phase A: x1 -> bf16 split tiles (thread owns d-pair, 2 nodes) ----
    {
        const int dp  = t & 63;
        const int d0  = dp * 2;
        const int grp = t >> 6;
        const float2 wc0 = *reinterpret_cast<const float2*>(&W1[(2 * CIN + 0) * HID + d0]);
        const float2 wc1 = *reinterpret_cast<const float2*>(&W1[(2 * CIN + 1) * HID + d0]);
        const float2 wc2 = *reinterpret_cast<const float2*>(&W1[(2 * CIN + 2) * HID + d0]);

        #pragma unroll
        for (int nn2 = 0; nn2 < 2; ++nn2) {
            const int nn   = grp * 2 + nn2;
            const int node = node0 + nn;
            const float2 a2 = *reinterpret_cast<const float2*>(&g_A[(size_t)node * HID + d0]);
            unsigned char* bhi = xs + nn * NODE_TILE + d0 * 2;
            unsigned char* blo = bhi + SPLIT_TILE;
            #pragma unroll
            for (int k = 0; k < KK; ++k) {
                const int e = nn * 16 + k;
                const float2 u2 = *reinterpret_cast<const float2*>(
                    &g_U[((size_t)b * NN + jidx[e]) * HID + d0]);
                const float4 r4 = *reinterpret_cast<const float4*>(&rel[e][0]);
                float x0 = a2.x + u2.x;
                x0 = fmaf(r4.x, wc0.x, x0);
                x0 = fmaf(r4.y, wc1.x, x0);
                x0 = fmaf(r4.z, wc2.x, x0);
                float x1 = a2.y + u2.y;
                x1 = fmaf(r4.x, wc0.y, x1);
                x1 = fmaf(r4.y, wc1.y, x1);
                x1 = fmaf(r4.z, wc2.y, x1);
                const float v0 = fast_gelu(x0);
                const float v1 = fast_gelu(x1);
                const uint32_t hbits = bf16x2_pack(v0, v1);
                const float h0f = __uint_as_float(hbits << 16);
                const float h1f = __uint_as_float(hbits & 0xffff0000u);
                *reinterpret_cast<uint32_t*>(bhi + k * ROWB) = hbits;
                *reinterpret_cast<uint32_t*>(blo + k * ROWB) = bf16x2_pack(v0 - h0f, v1 - h1f);
            }
        }
    }
    __syncthreads();

    // ---- phase B: warp wid = node wid ----
    const uint32_t abase = smem_u32(xs) + wid * NODE_TILE
                         + (lane & 15) * ROWB + (lane >> 4) * 16;
    uint32_t Ah[8][4];
    #pragma unroll
    for (int s = 0; s < 8; ++s) ldsm_x4(Ah[s], abase + s * 32);

    // min/max staging reuses the (now dead) hi-tile region of this warp's node
    float* mm = reinterpret_cast<float*>(xs + wid * NODE_TILE);   // [0..127]=min, [128..255]=max

    #pragma unroll
    for (int g = 0; g < 4; ++g) {
        float acc[4][4];
        #pragma unroll
        for (int j = 0; j < 4; ++j)
            #pragma unroll
            for (int i = 0; i < 4; ++i) acc[j][i] = 0.0f;

        #pragma unroll
        for (int s = 0; s < 8; ++s) {
            uint32_t bh[4][2], bl[4][2];
            #pragma unroll
            for (int j = 0; j < 4; ++j) {
                const int nt = g * 4 + j;
                const ulonglong2 w2 = g_Bfrag[(s * 16 + nt) * 32 + lane];   // LDG.128
                bh[j][0] = (uint32_t)w2.x; bh[j][1] = (uint32_t)(w2.x >> 32);
                bl[j][0] = (uint32_t)w2.y; bl[j][1] = (uint32_t)(w2.y >> 32);
            }
            uint32_t Alf[4];
            ldsm_x4(Alf, abase + SPLIT_TILE + s * 32);
            // interleave split-products across the 4 nt-tiles
            #pragma unroll
            for (int j = 0; j < 4; ++j) mma16816(acc[j], Ah[s], bh[j][0], bh[j][1]);
            #pragma unroll
            for (int j = 0; j < 4; ++j) mma16816(acc[j], Alf, bh[j][0], bh[j][1]);
            #pragma unroll
            for (int j = 0; j < 4; ++j) mma16816(acc[j], Ah[s], bl[j][0], bl[j][1]);
        }

        #pragma unroll
        for (int j = 0; j < 4; ++j) {
            const int nt = g * 4 + j;
            float mn0 = fminf(acc[j][0], acc[j][2]), mx0 = fmaxf(acc[j][0], acc[j][2]);
            float mn1 = fminf(acc[j][1], acc[j][3]), mx1 = fmaxf(acc[j][1], acc[j][3]);
            #pragma unroll
            for (int off = 4; off <= 16; off <<= 1) {
                mn0 = fminf(mn0, __shfl_xor_sync(0xffffffffu, mn0, off));
                mx0 = fmaxf(mx0, __shfl_xor_sync(0xffffffffu, mx0, off));
                mn1 = fminf(mn1, __shfl_xor_sync(0xffffffffu, mn1, off));
                mx1 = fmaxf(mx1, __shfl_xor_sync(0xffffffffu, mx1, off));
            }
            if (lane < 4) {
                const int cc = nt * 8 + lane * 2;
                *reinterpret_cast<float2*>(&mm[cc])       = make_float2(mn0, mn1);
                *reinterpret_cast<float2*>(&mm[128 + cc]) = make_float2(mx0, mx1);
            }
        }
    }
    __syncwarp();

    // ---- epilogue: lane owns 4 channels; unimodal gelu + in-warp LayerNorm ----
    const int cb4 = lane * 4;
    const float4 mn = *reinterpret_cast<const float4*>(&mm[cb4]);
    const float4 mx = *reinterpret_cast<const float4*>(&mm[128 + cb4]);
    const float4 bb = *reinterpret_cast<const float4*>(&b2[cb4]);
    float v[4];
    v[0] = fmaxf(fast_gelu(mn.x + bb.x), fast_gelu(mx.x + bb.x));
    v[1] = fmaxf(fast_gelu(mn.y + bb.y), fast_gelu(mx.y + bb.y));
    v[2] = fmaxf(fast_gelu(mn.z + bb.z), fast_gelu(mx.z + bb.z));
    v[3] = fmaxf(fast_gelu(mn.w + bb.w), fast_gelu(mx.w + bb.w));

    float s = v[0] + v[1] + v[2] + v[3];
    #pragma unroll
    for (int o = 16; o > 0; o >>= 1) s += __shfl_xor_sync(0xffffffffu, s, o);
    const float mean = s * (1.0f / COUT);

    float dv[4], q = 0.0f;
    #pragma unroll
    for (int i = 0; i < 4; ++i) { dv[i] = v[i] - mean; q = fmaf(dv[i], dv[i], q); }
    #pragma unroll
    for (int o = 16; o > 0; o >>= 1) q += __shfl_xor_sync(0xffffffffu, q, o);
    const float rstd = rsqrtf(q * (1.0f / COUT) + 1e-5f);

    const float4 gm = *reinterpret_cast<const float4*>(&gamma[cb4]);
    const float4 bt = *reinterpret_cast<const float4*>(&beta[cb4]);
    float4 o4;
    o4.x = dv[0] * rstd * gm.x + bt.x;
    o4.y = dv[1] * rstd * gm.y + bt.y;
    o4.z = dv[2] * rstd * gm.z + bt.z;
    o4.w = dv[3] * rstd * gm.w + bt.w;
    *reinterpret_cast<float4*>(&out[(size_t)(node0 + wid) * COUT + cb4]) = o4;
}

extern "C" void kernel_launch(void* const* d_in, const int* in_sizes, int n_in,
                              void* d_out, int out_size) {
    const float* h     = (const float*)d_in[0];
    const float* pos   = (const float*)d_in[1];
    const int*   idx   = (const int*)  d_in[2];
    const float* W1    = (const float*)d_in[3];
    const float* b1    = (const float*)d_in[4];
    const float* W2    = (const float*)d_in[5];
    const float* b2    = (const float*)d_in[6];
    const float* gamma = (const float*)d_in[7];
    const float* beta  = (const float*)d_in[8];
    float*       out   = (float*)d_out;

    precompute_kernel<<<NNODE / PN, 128>>>(h, W1, b1, W2, idx);
    edgeconv_mma_kernel<<<NNODE / NPB, 128>>>(pos, idx, W1, b2, gamma, beta, out);
}

// round 16
// speedup vs baseline: 1.0962x; 1.0962x over previous
#include <cuda_runtime.h>
#include <cuda_bf16.h>
#include <math.h>
#include <stdint.h>

#define BB   8
#define NN   2048
#define KK   16
#define CIN  128
#define HID  128
#define COUT 128
#define NNODE (BB * NN)
#define PN   8              // nodes per block in precompute
#define NPB  4              // nodes per block in main kernel
#define ROWB 272            // padded row bytes of x tile (17 x 16B -> LDSM conflict-free)
#define SPLIT_TILE (KK * ROWB)        // 4352 bytes per split
#define NODE_TILE  (2 * SPLIT_TILE)   // 8704 bytes per node (hi + lo)

// scratch: per-node projections  A = h@(W1a-W1b)+b1,  U = h@W1b
__device__ float g_A[NNODE * HID];
__device__ float g_U[NNODE * HID];
// W2, 2-way bf16 split, prepacked in mma.m16n8k16 B-fragment order.
// One 16B slot per (kstep, ntile, lane): .x = hi-split frag, .y = lo-split frag.
__device__ ulonglong2 g_Bfrag[8 * 16 * 32];
__device__ int g_idx_is64;

// ---- f32x2 helpers (precompute kernel) ----
__device__ __forceinline__ unsigned long long ffma2(unsigned long long a,
                                                    unsigned long long b,
                                                    unsigned long long c) {
    unsigned long long d;
    asm("fma.rn.f32x2 %0, %1, %2, %3;" : "=l"(d) : "l"(a), "l"(b), "l"(c));
    return d;
}
__device__ __forceinline__ unsigned long long pack2(float lo, float hi) {
    unsigned long long v;
    asm("mov.b64 %0, {%1, %2};" : "=l"(v) : "f"(lo), "f"(hi));
    return v;
}
__device__ __forceinline__ float2 unpack2(unsigned long long v) {
    float2 r;
    asm("mov.b64 {%0, %1}, %2;" : "=f"(r.x), "=f"(r.y) : "l"(v));
    return r;
}

// Branch-free gelu via Abramowitz-Stegun 7.1.26 erf (abs err <= 1.5e-7).
__device__ __forceinline__ float fast_gelu(float x) {
    const float z  = fabsf(x) * 0.70710678118654752440f;
    const float t  = __fdividef(1.0f, fmaf(0.3275911f, z, 1.0f));
    float p = fmaf(1.061405429f, t, -1.453152027f);
    p = fmaf(p, t, 1.421413741f);
    p = fmaf(p, t, -0.284496736f);
    p = fmaf(p, t, 0.254829592f);
    p = p * t;
    const float e = 1.0f - p * __expf(-z * z);
    return 0.5f * x * (1.0f + copysignf(e, x));
}

__device__ __forceinline__ uint32_t smem_u32(const void* p) {
    uint32_t a;
    asm("{ .reg .u64 t; cvta.to.shared.u64 t, %1; cvt.u32.u64 %0, t; }" : "=r"(a) : "l"(p));
    return a;
}

// ---- warp-level tensor core primitives (sm_80-era, valid on sm_103) ----
__device__ __forceinline__ void ldsm_x4(uint32_t* r, uint32_t addr) {
    asm volatile("ldmatrix.sync.aligned.m8n8.x4.shared.b16 {%0,%1,%2,%3}, [%4];"
                 : "=r"(r[0]), "=r"(r[1]), "=r"(r[2]), "=r"(r[3]) : "r"(addr));
}
__device__ __forceinline__ void mma16816(float* c, const uint32_t* a,
                                         uint32_t b0, uint32_t b1) {
    asm volatile("mma.sync.aligned.m16n8k16.row.col.f32.bf16.bf16.f32 "
                 "{%0,%1,%2,%3}, {%4,%5,%6,%7}, {%8,%9}, {%0,%1,%2,%3};"
                 : "+f"(c[0]), "+f"(c[1]), "+f"(c[2]), "+f"(c[3])
                 : "r"(a[0]), "r"(a[1]), "r"(a[2]), "r"(a[3]), "r"(b0), "r"(b1));
}

__device__ __forceinline__ uint32_t bf16x2_pack(float x, float y) {
    __nv_bfloat162 h = __floats2bfloat162_rn(x, y);   // .x = x in low half
    return *reinterpret_cast<uint32_t*>(&h);
}

// ---------------------------------------------------------------------------
// Precompute A = h@(W1a-W1b)+b1,  U = h@W1b.
// Block 0: idx dtype detect.  Blocks 0..63: also prepack one split-half of
// the W2 B-fragment slots (8-byte stores, spread thin like R14).
// ---------------------------------------------------------------------------
__global__ __launch_bounds__(128) void precompute_kernel(
    const float* __restrict__ h,
    const float* __restrict__ W1,
    const float* __restrict__ b1,
    const float* __restrict__ W2,
    const int*   __restrict__ idx_raw)
{
    __shared__ float hs[PN][CIN];
    const int t     = threadIdx.x;
    const int node0 = blockIdx.x * PN;

    if (blockIdx.x == 0 && t < 32) {
        int nz = (idx_raw[2 * t + 1] != 0) | (idx_raw[2 * (t + 32) + 1] != 0);
        unsigned m = __ballot_sync(0xffffffffu, nz);
        if (t == 0) g_idx_is64 = (m == 0u);
    }

    // ---- W2 B-fragment prepack, folded in (blocks 0..63, one 8B half each) ----
    if (blockIdx.x < 64) {
        const int flat = blockIdx.x * 128 + t;   // 0..8191
        const int sp   = flat >> 12;             // 0 = hi half, 1 = lo half
        const int slot = flat & 4095;
        const int lane = slot & 31;
        const int nt   = (slot >> 5) & 15;
        const int s    = slot >> 9;
        const int tg   = lane & 3;
        const int n    = nt * 8 + (lane >> 2);
        const int kloc[4] = {2 * tg, 2 * tg + 1, 2 * tg + 8, 2 * tg + 9};
        unsigned long long v = 0ull;
        #pragma unroll
        for (int e = 0; e < 4; ++e) {
            const float w = W2[(s * 16 + kloc[e]) * COUT + n];
            const __nv_bfloat16 hi = __float2bfloat16(w);
            __nv_bfloat16 val = hi;
            if (sp == 1) val = __float2bfloat16(w - __bfloat162float(hi));
            v |= (unsigned long long)(*reinterpret_cast<const unsigned short*>(&val)) << (16 * e);
        }
        reinterpret_cast<unsigned long long*>(&g_Bfrag[slot])[sp] = v;
    }

    #pragma unroll
    for (int i = 0; i < PN; ++i)
        hs[i][t] = h[(size_t)(node0 + i) * CIN + t];
    __syncthreads();

    unsigned long long accA[PN], accU[PN];
    #pragma unroll
    for (int i = 0; i < PN; ++i) { accA[i] = 0ull; accU[i] = 0ull; }

    #pragma unroll 2
    for (int dd = 0; dd < CIN / 4; ++dd) {
        const int d0 = 4 * dd;
        float w1a[4], w1b[4];
        #pragma unroll
        for (int j = 0; j < 4; ++j) {
            w1a[j] = W1[(d0 + j) * HID + t];
            w1b[j] = W1[(CIN + d0 + j) * HID + t];
        }
        const unsigned long long wa01 = pack2(w1a[0] - w1b[0], w1a[1] - w1b[1]);
        const unsigned long long wa23 = pack2(w1a[2] - w1b[2], w1a[3] - w1b[3]);
        const unsigned long long wb01 = pack2(w1b[0], w1b[1]);
        const unsigned long long wb23 = pack2(w1b[2], w1b[3]);
        #pragma unroll
        for (int i = 0; i < PN; ++i) {
            const ulonglong2 m2 = *reinterpret_cast<const ulonglong2*>(&hs[i][d0]);
            accA[i] = ffma2(m2.x, wa01, accA[i]);
            accA[i] = ffma2(m2.y, wa23, accA[i]);
            accU[i] = ffma2(m2.x, wb01, accU[i]);
            accU[i] = ffma2(m2.y, wb23, accU[i]);
        }
    }
    const float bv = b1[t];
    #pragma unroll
    for (int i = 0; i < PN; ++i) {
        const float2 a2 = unpack2(accA[i]);
        const float2 u2 = unpack2(accU[i]);
        g_A[(size_t)(node0 + i) * HID + t] = a2.x + a2.y + bv;
        g_U[(size_t)(node0 + i) * HID + t] = u2.x + u2.y;
    }
}

// ---------------------------------------------------------------------------
// Main kernel: 4 nodes per block, 128 threads, FULLY WARP-INDEPENDENT:
// each warp owns one node end-to-end (jidx, rel, gather+gelu tile build,
// HMMA, epilogue). No __syncthreads — only __syncwarp. Warps at different
// phases overlap each other's latency.
// ---------------------------------------------------------------------------
__global__ __launch_bounds__(128, 6) void edgeconv_mma_kernel(
    const float* __restrict__ pos,
    const int*   __restrict__ idx_raw,
    const float* __restrict__ W1,      // rows 256..258 (rel weights)
    const float* __restrict__ b2,
    const float* __restrict__ gamma,
    const float* __restrict__ beta,
    float*       __restrict__ out)
{
    __shared__ __align__(16) unsigned char xs[NPB * NODE_TILE];   // 34816 B
    __shared__ int   jidx[NPB * KK];
    __shared__ __align__(16) float rel[NPB * KK][4];

    const int t     = threadIdx.x;
    const int lane  = t & 31;
    const int wid   = t >> 5;
    const int node0 = blockIdx.x * NPB;
    const int node  = node0 + wid;               // this warp's node
    const int b     = node0 >> 11;
    const int n     = node & (NN - 1);
    const float* pb = pos + (size_t)b * NN * 3;
    const int ebase = wid * KK;

    // ---- neighbor indices (this warp's 16) ----
    if (lane < KK) {
        long e = (long)node * KK + lane;
        jidx[ebase + lane] = g_idx_is64 ? idx_raw[2 * e] : idx_raw[e];
    }
    __syncwarp();

    // ---- relative positions (48 entries, 32 lanes -> 2 passes) ----
    for (int s = lane; s < KK * 3; s += 32) {
        const int e = s / 3, c = s - 3 * e;
        rel[ebase + e][c] = pb[jidx[ebase + e] * 3 + c] - pb[n * 3 + c];
    }
    __syncwarp();

    // ---- phase A: x1 -> bf16 split tiles (lane owns 2 d-pairs, own node) ----
    {
        unsigned char* tile = xs + wid * NODE_TILE;
        #pragma unroll
        for (int half = 0; half < 2; ++half) {
            const int d0 = (lane + half * 32) * 2;
            const float2 wc0 = *reinterpret_cast<const float2*>(&W1[(2 * CIN + 0) * HID + d0]);
            const float2 wc1 = *reinterpret_cast<const float2*>(&W1[(2 * CIN + 1) * HID + d0]);
            const float2 wc2 = *reinterpret_cast<const float2*>(&W1[(2 * CIN + 2) * HID + d0]);
            const float2 a2  = *reinterpret_cast<const float2*>(&g_A[(size_t)node * HID + d0]);
            unsigned char* bhi = tile + d0 * 2;
            unsigned char* blo = bhi + SPLIT_TILE;
            #pragma unroll
            for (int k = 0; k < KK; ++k) {
                const float2 u2 = *reinterpret_cast<const float2*>(
                    &g_U[((size_t)b * NN + jidx[ebase + k]) * HID + d0]);
                const float4 r4 = *reinterpret_cast<const float4*>(&rel[ebase + k][0]);
                float x0 = a2.x + u2.x;
                x0 = fmaf(r4.x, wc0.x, x0);
                x0 = fmaf(r4.y, wc1.x, x0);
                x0 = fmaf(r4.z, wc2.x, x0);
                float x1 = a2.y + u2.y;
                x1 = fmaf(r4.x, wc0.y, x1);
                x1 = fmaf(r4.y, wc1.y, x1);
                x1 = fmaf(r4.z, wc2.y, x1);
                const float v0 = fast_gelu(x0);
                const float v1 = fast_gelu(x1);
                const uint32_t hbits = bf16x2_pack(v0, v1);
                const float h0f = __uint_as_float(hbits << 16);
                const float h1f = __uint_as_float(hbits & 0xffff0000u);
                *reinterpret_cast<uint32_t*>(bhi + k * ROWB) = hbits;
                *reinterpret_cast<uint32_t*>(blo + k * ROWB) = bf16x2_pack(v0 - h0f, v1 - h1f);
            }
        }
    }
    __syncwarp();

    // ---- phase B ----
    const uint32_t abase = smem_u32(xs) + wid * NODE_TILE
                         + (lane & 15) * ROWB + (lane >> 4) * 16;
    uint32_t Ah[8][4];
    #pragma unroll
    for (int s = 0; s < 8; ++s) ldsm_x4(Ah[s], abase + s * 32);

    // min/max staging reuses the (now dead) hi-tile region of this warp's node
    float* mm = reinterpret_cast<float*>(xs + wid * NODE_TILE);   // [0..127]=min, [128..255]=max

    #pragma unroll
    for (int g = 0; g < 4; ++g) {
        float acc[4][4];
        #pragma unroll
        for (int j = 0; j < 4; ++j)
            #pragma unroll
            for (int i = 0; i < 4; ++i) acc[j][i] = 0.0f;

        #pragma unroll
        for (int s = 0; s < 8; ++s) {
            uint32_t bh[4][2], bl[4][2];
            #pragma unroll
            for (int j = 0; j < 4; ++j) {
                const int nt = g * 4 + j;
                const ulonglong2 w2 = g_Bfrag[(s * 16 + nt) * 32 + lane];   // LDG.128
                bh[j][0] = (uint32_t)w2.x; bh[j][1] = (uint32_t)(w2.x >> 32);
                bl[j][0] = (uint32_t)w2.y; bl[j][1] = (uint32_t)(w2.y >> 32);
            }
            uint32_t Alf[4];
            ldsm_x4(Alf, abase + SPLIT_TILE + s * 32);
            // interleave split-products across the 4 nt-tiles
            #pragma unroll
            for (int j = 0; j < 4; ++j) mma16816(acc[j], Ah[s], bh[j][0], bh[j][1]);
            #pragma unroll
            for (int j = 0; j < 4; ++j) mma16816(acc[j], Alf, bh[j][0], bh[j][1]);
            #pragma unroll
            for (int j = 0; j < 4; ++j) mma16816(acc[j], Ah[s], bl[j][0], bl[j][1]);
        }

        #pragma unroll
        for (int j = 0; j < 4; ++j) {
            const int nt = g * 4 + j;
            float mn0 = fminf(acc[j][0], acc[j][2]), mx0 = fmaxf(acc[j][0], acc[j][2]);
            float mn1 = fminf(acc[j][1], acc[j][3]), mx1 = fmaxf(acc[j][1], acc[j][3]);
            #pragma unroll
            for (int off = 4; off <= 16; off <<= 1) {
                mn0 = fminf(mn0, __shfl_xor_sync(0xffffffffu, mn0, off));
                mx0 = fmaxf(mx0, __shfl_xor_sync(0xffffffffu, mx0, off));
                mn1 = fminf(mn1, __shfl_xor_sync(0xffffffffu, mn1, off));
                mx1 = fmaxf(mx1, __shfl_xor_sync(0xffffffffu, mx1, off));
            }
            if (lane < 4) {
                const int cc = nt * 8 + lane * 2;
                *reinterpret_cast<float2*>(&mm[cc])       = make_float2(mn0, mn1);
                *reinterpret_cast<float2*>(&mm[128 + cc]) = make_float2(mx0, mx1);
            }
        }
    }
    __syncwarp();

    // ---- epilogue: lane owns 4 channels; unimodal gelu + in-warp LayerNorm ----
    const int cb4 = lane * 4;
    const float4 mn = *reinterpret_cast<const float4*>(&mm[cb4]);
    const float4 mx = *reinterpret_cast<const float4*>(&mm[128 + cb4]);
    const float4 bb = *reinterpret_cast<const float4*>(&b2[cb4]);
    float v[4];
    v[0] = fmaxf(fast_gelu(mn.x + bb.x), fast_gelu(mx.x + bb.x));
    v[1] = fmaxf(fast_gelu(mn.y + bb.y), fast_gelu(mx.y + bb.y));
    v[2] = fmaxf(fast_gelu(mn.z + bb.z), fast_gelu(mx.z + bb.z));
    v[3] = fmaxf(fast_gelu(mn.w + bb.w), fast_gelu(mx.w + bb.w));

    float s = v[0] + v[1] + v[2] + v[3];
    #pragma unroll
    for (int o = 16; o > 0; o >>= 1) s += __shfl_xor_sync(0xffffffffu, s, o);
    const float mean = s * (1.0f / COUT);

    float dv[4], q = 0.0f;
    #pragma unroll
    for (int i = 0; i < 4; ++i) { dv[i] = v[i] - mean; q = fmaf(dv[i], dv[i], q); }
    #pragma unroll
    for (int o = 16; o > 0; o >>= 1) q += __shfl_xor_sync(0xffffffffu, q, o);
    const float rstd = rsqrtf(q * (1.0f / COUT) + 1e-5f);

    const float4 gm = *reinterpret_cast<const float4*>(&gamma[cb4]);
    const float4 bt = *reinterpret_cast<const float4*>(&beta[cb4]);
    float4 o4;
    o4.x = dv[0] * rstd * gm.x + bt.x;
    o4.y = dv[1] * rstd * gm.y + bt.y;
    o4.z = dv[2] * rstd * gm.z + bt.z;
    o4.w = dv[3] * rstd * gm.w + bt.w;
    *reinterpret_cast<float4*>(&out[(size_t)node * COUT + cb4]) = o4;
}

extern "C" void kernel_launch(void* const* d_in, const int* in_sizes, int n_in,
                              void* d_out, int out_size) {
    const float* h     = (const float*)d_in[0];
    const float* pos   = (const float*)d_in[1];
    const int*   idx   = (const int*)  d_in[2];
    const float* W1    = (const float*)d_in[3];
    const float* b1    = (const float*)d_in[4];
    const float* W2    = (const float*)d_in[5];
    const float* b2    = (const float*)d_in[6];
    const float* gamma = (const float*)d_in[7];
    const float* beta  = (const float*)d_in[8];
    float*       out   = (float*)d_out;

    precompute_kernel<<<NNODE / PN, 128>>>(h, W1, b1, W2, idx);
    edgeconv_mma_kernel<<<NNODE / NPB, 128>>>(pos, idx, W1, b2, gamma, beta, out);
}

// round 17
// speedup vs baseline: 1.1490x; 1.0482x over previous
#include <cuda_runtime.h>
#include <cuda_bf16.h>
#include <math.h>
#include <stdint.h>

#define BB   8
#define NN   2048
#define KK   16
#define CIN  128
#define HID  128
#define COUT 128
#define NNODE (BB * NN)
#define PN   8              // nodes per block in precompute
#define NPB  4              // nodes per block in main kernel
#define ROWB 272            // padded row bytes of x tile (17 x 16B -> LDSM conflict-free)
#define SPLIT_TILE (KK * ROWB)        // 4352 bytes per split
#define NODE_TILE  (2 * SPLIT_TILE)   // 8704 bytes per node (hi + lo)

// scratch: per-node projections  A = h@(W1a-W1b)+b1,  U = h@W1b
__device__ float g_A[NNODE * HID];
__device__ float g_U[NNODE * HID];
// W2, 2-way bf16 split, prepacked in mma.m16n8k16 B-fragment order.
// One 16B slot per (kstep, ntile, lane): .x = hi-split frag, .y = lo-split frag.
__device__ ulonglong2 g_Bfrag[8 * 16 * 32];
__device__ int g_idx_is64;

// ---- f32x2 helpers (precompute kernel) ----
__device__ __forceinline__ unsigned long long ffma2(unsigned long long a,
                                                    unsigned long long b,
                                                    unsigned long long c) {
    unsigned long long d;
    asm("fma.rn.f32x2 %0, %1, %2, %3;" : "=l"(d) : "l"(a), "l"(b), "l"(c));
    return d;
}
__device__ __forceinline__ unsigned long long pack2(float lo, float hi) {
    unsigned long long v;
    asm("mov.b64 %0, {%1, %2};" : "=l"(v) : "f"(lo), "f"(hi));
    return v;
}
__device__ __forceinline__ float2 unpack2(unsigned long long v) {
    float2 r;
    asm("mov.b64 {%0, %1}, %2;" : "=f"(r.x), "=f"(r.y) : "l"(v));
    return r;
}

// Branch-free gelu via Abramowitz-Stegun 7.1.26 erf (abs err <= 1.5e-7).
__device__ __forceinline__ float fast_gelu(float x) {
    const float z  = fabsf(x) * 0.70710678118654752440f;
    const float t  = __fdividef(1.0f, fmaf(0.3275911f, z, 1.0f));
    float p = fmaf(1.061405429f, t, -1.453152027f);
    p = fmaf(p, t, 1.421413741f);
    p = fmaf(p, t, -0.284496736f);
    p = fmaf(p, t, 0.254829592f);
    p = p * t;
    const float e = 1.0f - p * __expf(-z * z);
    return 0.5f * x * (1.0f + copysignf(e, x));
}

__device__ __forceinline__ uint32_t smem_u32(const void* p) {
    uint32_t a;
    asm("{ .reg .u64 t; cvta.to.shared.u64 t, %1; cvt.u32.u64 %0, t; }" : "=r"(a) : "l"(p));
    return a;
}

// ---- warp-level tensor core primitives (sm_80-era, valid on sm_103) ----
__device__ __forceinline__ void ldsm_x4(uint32_t* r, uint32_t addr) {
    asm volatile("ldmatrix.sync.aligned.m8n8.x4.shared.b16 {%0,%1,%2,%3}, [%4];"
                 : "=r"(r[0]), "=r"(r[1]), "=r"(r[2]), "=r"(r[3]) : "r"(addr));
}
__device__ __forceinline__ void mma16816(float* c, const uint32_t* a,
                                         uint32_t b0, uint32_t b1) {
    asm volatile("mma.sync.aligned.m16n8k16.row.col.f32.bf16.bf16.f32 "
                 "{%0,%1,%2,%3}, {%4,%5,%6,%7}, {%8,%9}, {%0,%1,%2,%3};"
                 : "+f"(c[0]), "+f"(c[1]), "+f"(c[2]), "+f"(c[3])
                 : "r"(a[0]), "r"(a[1]), "r"(a[2]), "r"(a[3]), "r"(b0), "r"(b1));
}

__device__ __forceinline__ uint32_t bf16x2_pack(float x, float y) {
    __nv_bfloat162 h = __floats2bfloat162_rn(x, y);   // .x = x in low half
    return *reinterpret_cast<uint32_t*>(&h);
}

// ---------------------------------------------------------------------------
// Precompute A = h@(W1a-W1b)+b1,  U = h@W1b.
// Block 0: idx dtype detect.  Blocks 0..63: also prepack one split-half of
// the W2 B-fragment slots (8-byte stores, spread thin).
// ---------------------------------------------------------------------------
__global__ __launch_bounds__(128) void precompute_kernel(
    const float* __restrict__ h,
    const float* __restrict__ W1,
    const float* __restrict__ b1,
    const float* __restrict__ W2,
    const int*   __restrict__ idx_raw)
{
    __shared__ float hs[PN][CIN];
    const int t     = threadIdx.x;
    const int node0 = blockIdx.x * PN;

    if (blockIdx.x == 0 && t < 32) {
        int nz = (idx_raw[2 * t + 1] != 0) | (idx_raw[2 * (t + 32) + 1] != 0);
        unsigned m = __ballot_sync(0xffffffffu, nz);
        if (t == 0) g_idx_is64 = (m == 0u);
    }

    // ---- W2 B-fragment prepack, folded in (blocks 0..63, one 8B half each) ----
    if (blockIdx.x < 64) {
        const int flat = blockIdx.x * 128 + t;   // 0..8191
        const int sp   = flat >> 12;             // 0 = hi half, 1 = lo half
        const int slot = flat & 4095;
        const int lane = slot & 31;
        const int nt   = (slot >> 5) & 15;
        const int s    = slot >> 9;
        const int tg   = lane & 3;
        const int n    = nt * 8 + (lane >> 2);
        const int kloc[4] = {2 * tg, 2 * tg + 1, 2 * tg + 8, 2 * tg + 9};
        unsigned long long v = 0ull;
        #pragma unroll
        for (int e = 0; e < 4; ++e) {
            const float w = W2[(s * 16 + kloc[e]) * COUT + n];
            const __nv_bfloat16 hi = __float2bfloat16(w);
            __nv_bfloat16 val = hi;
            if (sp == 1) val = __float2bfloat16(w - __bfloat162float(hi));
            v |= (unsigned long long)(*reinterpret_cast<const unsigned short*>(&val)) << (16 * e);
        }
        reinterpret_cast<unsigned long long*>(&g_Bfrag[slot])[sp] = v;
    }

    #pragma unroll
    for (int i = 0; i < PN; ++i)
        hs[i][t] = h[(size_t)(node0 + i) * CIN + t];
    __syncthreads();

    unsigned long long accA[PN], accU[PN];
    #pragma unroll
    for (int i = 0; i < PN; ++i) { accA[i] = 0ull; accU[i] = 0ull; }

    #pragma unroll 2
    for (int dd = 0; dd < CIN / 4; ++dd) {
        const int d0 = 4 * dd;
        float w1a[4], w1b[4];
        #pragma unroll
        for (int j = 0; j < 4; ++j) {
            w1a[j] = W1[(d0 + j) * HID + t];
            w1b[j] = W1[(CIN + d0 + j) * HID + t];
        }
        const unsigned long long wa01 = pack2(w1a[0] - w1b[0], w1a[1] - w1b[1]);
        const unsigned long long wa23 = pack2(w1a[2] - w1b[2], w1a[3] - w1b[3]);
        const unsigned long long wb01 = pack2(w1b[0], w1b[1]);
        const unsigned long long wb23 = pack2(w1b[2], w1b[3]);
        #pragma unroll
        for (int i = 0; i < PN; ++i) {
            const ulonglong2 m2 = *reinterpret_cast<const ulonglong2*>(&hs[i][d0]);
            accA[i] = ffma2(m2.x, wa01, accA[i]);
            accA[i] = ffma2(m2.y, wa23, accA[i]);
            accU[i] = ffma2(m2.x, wb01, accU[i]);
            accU[i] = ffma2(m2.y, wb23, accU[i]);
        }
    }
    const float bv = b1[t];
    #pragma unroll
    for (int i = 0; i < PN; ++i) {
        const float2 a2 = unpack2(accA[i]);
        const float2 u2 = unpack2(accU[i]);
        g_A[(size_t)(node0 + i) * HID + t] = a2.x + a2.y + bv;
        g_U[(size_t)(node0 + i) * HID + t] = u2.x + u2.y;
    }
}

// ---------------------------------------------------------------------------
// Main kernel: 4 nodes per block, 128 threads, fully warp-independent.
// Phase A (lane owns a d-QUAD, single 16-k pass): 16 LDG.128 gathers,
//         32 STS.64 tile writes — half the memory instructions of the
//         d-pair scheme at identical byte traffic and identical values.
// Phase B unchanged: hoisted Ah, Al re-ldsm, B-frag LDG.128, interleaved
//         split-product HMMA, min/max over M, unimodal fast_gelu, warp LN.
// ---------------------------------------------------------------------------
__global__ __launch_bounds__(128, 6) void edgeconv_mma_kernel(
    const float* __restrict__ pos,
    const int*   __restrict__ idx_raw,
    const float* __restrict__ W1,      // rows 256..258 (rel weights)
    const float* __restrict__ b2,
    const float* __restrict__ gamma,
    const float* __restrict__ beta,
    float*       __restrict__ out)
{
    __shared__ __align__(16) unsigned char xs[NPB * NODE_TILE];   // 34816 B
    __shared__ int   jidx[NPB * KK];
    __shared__ __align__(16) float rel[NPB * KK][4];

    const int t     = threadIdx.x;
    const int lane  = t & 31;
    const int wid   = t >> 5;
    const int node0 = blockIdx.x * NPB;
    const int node  = node0 + wid;               // this warp's node
    const int b     = node0 >> 11;
    const int n     = node & (NN - 1);
    const float* pb = pos + (size_t)b * NN * 3;
    const int ebase = wid * KK;

    // ---- neighbor indices (this warp's 16) ----
    if (lane < KK) {
        long e = (long)node * KK + lane;
        jidx[ebase + lane] = g_idx_is64 ? idx_raw[2 * e] : idx_raw[e];
    }
    __syncwarp();

    // ---- relative positions (48 entries, 32 lanes -> 2 passes) ----
    for (int s = lane; s < KK * 3; s += 32) {
        const int e = s / 3, c = s - 3 * e;
        rel[ebase + e][c] = pb[jidx[ebase + e] * 3 + c] - pb[n * 3 + c];
    }
    __syncwarp();

    // ---- phase A: x1 -> bf16 split tiles (lane owns d-quad d0=lane*4) ----
    {
        const int d0 = lane * 4;
        const float4 wc0 = *reinterpret_cast<const float4*>(&W1[(2 * CIN + 0) * HID + d0]);
        const float4 wc1 = *reinterpret_cast<const float4*>(&W1[(2 * CIN + 1) * HID + d0]);
        const float4 wc2 = *reinterpret_cast<const float4*>(&W1[(2 * CIN + 2) * HID + d0]);
        const float4 a4  = *reinterpret_cast<const float4*>(&g_A[(size_t)node * HID + d0]);
        unsigned char* bhi = xs + wid * NODE_TILE + d0 * 2;
        unsigned char* blo = bhi + SPLIT_TILE;
        const float* gU = g_U + (size_t)b * NN * HID + d0;

        #pragma unroll
        for (int k = 0; k < KK; ++k) {
            const float4 u4 = *reinterpret_cast<const float4*>(&gU[(size_t)jidx[ebase + k] * HID]);
            const float4 r4 = *reinterpret_cast<const float4*>(&rel[ebase + k][0]);
            float x0 = a4.x + u4.x, x1 = a4.y + u4.y, x2 = a4.z + u4.z, x3 = a4.w + u4.w;
            x0 = fmaf(r4.x, wc0.x, x0); x0 = fmaf(r4.y, wc1.x, x0); x0 = fmaf(r4.z, wc2.x, x0);
            x1 = fmaf(r4.x, wc0.y, x1); x1 = fmaf(r4.y, wc1.y, x1); x1 = fmaf(r4.z, wc2.y, x1);
            x2 = fmaf(r4.x, wc0.z, x2); x2 = fmaf(r4.y, wc1.z, x2); x2 = fmaf(r4.z, wc2.z, x2);
            x3 = fmaf(r4.x, wc0.w, x3); x3 = fmaf(r4.y, wc1.w, x3); x3 = fmaf(r4.z, wc2.w, x3);
            const float v0 = fast_gelu(x0);
            const float v1 = fast_gelu(x1);
            const float v2 = fast_gelu(x2);
            const float v3 = fast_gelu(x3);
            const uint32_t h01 = bf16x2_pack(v0, v1);
            const uint32_t h23 = bf16x2_pack(v2, v3);
            const float f0 = __uint_as_float(h01 << 16);
            const float f1 = __uint_as_float(h01 & 0xffff0000u);
            const float f2 = __uint_as_float(h23 << 16);
            const float f3 = __uint_as_float(h23 & 0xffff0000u);
            const uint32_t l01 = bf16x2_pack(v0 - f0, v1 - f1);
            const uint32_t l23 = bf16x2_pack(v2 - f2, v3 - f3);
            *reinterpret_cast<uint2*>(bhi + k * ROWB) = make_uint2(h01, h23);
            *reinterpret_cast<uint2*>(blo + k * ROWB) = make_uint2(l01, l23);
        }
    }
    __syncwarp();

    // ---- phase B ----
    const uint32_t abase = smem_u32(xs) + wid * NODE_TILE
                         + (lane & 15) * ROWB + (lane >> 4) * 16;
    uint32_t Ah[8][4];
    #pragma unroll
    for (int s = 0; s < 8; ++s) ldsm_x4(Ah[s], abase + s * 32);

    // min/max staging reuses the (now dead) hi-tile region of this warp's node
    float* mm = reinterpret_cast<float*>(xs + wid * NODE_TILE);   // [0..127]=min, [128..255]=max

    #pragma unroll
    for (int g = 0; g < 4; ++g) {
        float acc[4][4];
        #pragma unroll
        for (int j = 0; j < 4; ++j)
            #pragma unroll
            for (int i = 0; i < 4; ++i) acc[j][i] = 0.0f;

        #pragma unroll
        for (int s = 0; s < 8; ++s) {
            uint32_t bh[4][2], bl[4][2];
            #pragma unroll
            for (int j = 0; j < 4; ++j) {
                const int nt = g * 4 + j;
                const ulonglong2 w2 = g_Bfrag[(s * 16 + nt) * 32 + lane];   // LDG.128
                bh[j][0] = (uint32_t)w2.x; bh[j][1] = (uint32_t)(w2.x >> 32);
                bl[j][0] = (uint32_t)w2.y; bl[j][1] = (uint32_t)(w2.y >> 32);
            }
            uint32_t Alf[4];
            ldsm_x4(Alf, abase + SPLIT_TILE + s * 32);
            // interleave split-products across the 4 nt-tiles
            #pragma unroll
            for (int j = 0; j < 4; ++j) mma16816(acc[j], Ah[s], bh[j][0], bh[j][1]);
            #pragma unroll
            for (int j = 0; j < 4; ++j) mma16816(acc[j], Alf, bh[j][0], bh[j][1]);
            #pragma unroll
            for (int j = 0; j < 4; ++j) mma16816(acc[j], Ah[s], bl[j][0], bl[j][1]);
        }

        #pragma unroll
        for (int j = 0; j < 4; ++j) {
            const int nt = g * 4 + j;
            float mn0 = fminf(acc[j][0], acc[j][2]), mx0 = fmaxf(acc[j][0], acc[j][2]);
            float mn1 = fminf(acc[j][1], acc[j][3]), mx1 = fmaxf(acc[j][1], acc[j][3]);
            #pragma unroll
            for (int off = 4; off <= 16; off <<= 1) {
                mn0 = fminf(mn0, __shfl_xor_sync(0xffffffffu, mn0, off));
                mx0 = fmaxf(mx0, __shfl_xor_sync(0xffffffffu, mx0, off));
                mn1 = fminf(mn1, __shfl_xor_sync(0xffffffffu, mn1, off));
                mx1 = fmaxf(mx1, __shfl_xor_sync(0xffffffffu, mx1, off));
            }
            if (lane < 4) {
                const int cc = nt * 8 + lane * 2;
                *reinterpret_cast<float2*>(&mm[cc])       = make_float2(mn0, mn1);
                *reinterpret_cast<float2*>(&mm[128 + cc]) = make_float2(mx0, mx1);
            }
        }
    }
    __syncwarp();

    // ---- epilogue: lane owns 4 channels; unimodal gelu + in-warp LayerNorm ----
    const int cb4 = lane * 4;
    const float4 mn = *reinterpret_cast<const float4*>(&mm[cb4]);
    const float4 mx = *reinterpret_cast<const float4*>(&mm[128 + cb4]);
    const float4 bb = *reinterpret_cast<const float4*>(&b2[cb4]);
    float v[4];
    v[0] = fmaxf(fast_gelu(mn.x + bb.x), fast_gelu(mx.x + bb.x));
    v[1] = fmaxf(fast_gelu(mn.y + bb.y), fast_gelu(mx.y + bb.y));
    v[2] = fmaxf(fast_gelu(mn.z + bb.z), fast_gelu(mx.z + bb.z));
    v[3] = fmaxf(fast_gelu(mn.w + bb.w), fast_gelu(mx.w + bb.w));

    float s = v[0] + v[1] + v[2] + v[3];
    #pragma unroll
    for (int o = 16; o > 0; o >>= 1) s += __shfl_xor_sync(0xffffffffu, s, o);
    const float mean = s * (1.0f / COUT);

    float dv[4], q = 0.0f;
    #pragma unroll
    for (int i = 0; i < 4; ++i) { dv[i] = v[i] - mean; q = fmaf(dv[i], dv[i], q); }
    #pragma unroll
    for (int o = 16; o > 0; o >>= 1) q += __shfl_xor_sync(0xffffffffu, q, o);
    const float rstd = rsqrtf(q * (1.0f / COUT) + 1e-5f);

    const float4 gm = *reinterpret_cast<const float4*>(&gamma[cb4]);
    const float4 bt = *reinterpret_cast<const float4*>(&beta[cb4]);
    float4 o4;
    o4.x = dv[0] * rstd * gm.x + bt.x;
    o4.y = dv[1] * rstd * gm.y + bt.y;
    o4.z = dv[2] * rstd * gm.z + bt.z;
    o4.w = dv[3] * rstd * gm.w + bt.w;
    *reinterpret_cast<float4*>(&out[(size_t)node * COUT + cb4]) = o4;
}

extern "C" void kernel_launch(void* const* d_in, const int* in_sizes, int n_in,
                              void* d_out, int out_size) {
    const float* h     = (const float*)d_in[0];
    const float* pos   = (const float*)d_in[1];
    const int*   idx   = (const int*)  d_in[2];
    const float* W1    = (const float*)d_in[3];
    const float* b1    = (const float*)d_in[4];
    const float* W2    = (const float*)d_in[5];
    const float* b2    = (const float*)d_in[6];
    const float* gamma = (const float*)d_in[7];
    const float* beta  = (const float*)d_in[8];
    float*       out   = (float*)d_out;

    precompute_kernel<<<NNODE / PN, 128>>>(h, W1, b1, W2, idx);
    edgeconv_mma_kernel<<<NNODE / NPB, 128>>>(pos, idx, W1, b2, gamma, beta, out);
}